// round 1
// baseline (speedup 1.0000x reference)
#include <cuda_runtime.h>
#include <cstdint>

#define DEV_INLINE __device__ __forceinline__

// Problem constants
constexpr int B  = 32;
constexpr int S  = 512;
constexpr int D  = 512;
constexpr int NS = 5;

// Recurrent kernel tiling
constexpr int RANKS     = 8;            // CTAs per cluster
constexpr int BPC       = 2;            // batches per cluster
constexpr int NCLUSTERS = B / BPC;      // 16
constexpr int COLS      = D / RANKS;    // 64 output columns per CTA
constexpr int RTHREADS  = 512;

// Scratch (static device arrays; no allocations allowed)
__device__ float g_A[(size_t)B * S * D];       // H @ W1
__device__ float g_C[(size_t)B * S * D];       // H @ W2
__device__ float g_ht[B * D];                  // current htilde, full vectors
__device__ float g_Spart[B * NS * RANKS];      // per-rank partial logits

// ---------- packed f32x2 helpers ----------
DEV_INLINE uint64_t pack2(float lo, float hi) {
    uint64_t r; asm("mov.b64 %0, {%1, %2};" : "=l"(r) : "f"(lo), "f"(hi)); return r;
}
DEV_INLINE void unpack2(uint64_t v, float& lo, float& hi) {
    asm("mov.b64 {%0, %1}, %2;" : "=f"(lo), "=f"(hi) : "l"(v));
}
DEV_INLINE uint64_t fma2(uint64_t a, uint64_t b, uint64_t c) {
    uint64_t d; asm("fma.rn.f32x2 %0, %1, %2, %3;" : "=l"(d) : "l"(a), "l"(b), "l"(c));
    return d;
}

// ============================================================
// Precompute: A = H @ W1, C = H @ W2   (fp32, f32x2 FMAs)
// M = B*S = 16384, K = 512, N = 512 per weight
// Tile 128x128, BK=16, 256 threads, 8x8 per thread
// ============================================================
constexpr int PM = 128, PN = 128, PK = 16;

__global__ __launch_bounds__(256) void precompute_kernel(
    const float* __restrict__ Hm,
    const float* __restrict__ W1,
    const float* __restrict__ W2)
{
    __shared__ float As[PK][PM];
    __shared__ float Bs[PK][PN];

    const int tid   = threadIdx.x;
    const int which = blockIdx.y >> 2;          // 0 -> W1/A, 1 -> W2/C
    const int n0    = (blockIdx.y & 3) * PN;
    const int m0    = blockIdx.x * PM;
    const float* W  = which ? W2 : W1;
    float* OUT      = which ? g_C : g_A;

    const int tx = tid & 15;       // 0..15 (n direction)
    const int ty = tid >> 4;       // 0..15 (m direction)

    uint64_t acc[8][4];
    #pragma unroll
    for (int i = 0; i < 8; i++)
        #pragma unroll
        for (int j = 0; j < 4; j++) acc[i][j] = 0ull;

    for (int kt = 0; kt < 512; kt += PK) {
        // Load H tile -> As[k][m] (transposed)
        #pragma unroll
        for (int i = 0; i < 2; i++) {
            int idx4 = i * 256 + tid;
            int m  = idx4 >> 2;
            int kq = (idx4 & 3) * 4;
            float4 vv = *(const float4*)&Hm[(size_t)(m0 + m) * 512 + kt + kq];
            As[kq + 0][m] = vv.x; As[kq + 1][m] = vv.y;
            As[kq + 2][m] = vv.z; As[kq + 3][m] = vv.w;
        }
        // Load W tile -> Bs[k][n]
        #pragma unroll
        for (int i = 0; i < 2; i++) {
            int idx4 = i * 256 + tid;
            int n4 = (idx4 & 31) * 4;
            int k  = idx4 >> 5;
            *(float4*)&Bs[k][n4] = *(const float4*)&W[(size_t)(kt + k) * 512 + n0 + n4];
        }
        __syncthreads();

        #pragma unroll
        for (int k = 0; k < PK; k++) {
            float4 a0 = *(const float4*)&As[k][ty * 8];
            float4 a1 = *(const float4*)&As[k][ty * 8 + 4];
            float4 b0 = *(const float4*)&Bs[k][tx * 8];
            float4 b1 = *(const float4*)&Bs[k][tx * 8 + 4];
            float av[8] = {a0.x, a0.y, a0.z, a0.w, a1.x, a1.y, a1.z, a1.w};
            uint64_t bp[4];
            bp[0] = pack2(b0.x, b0.y); bp[1] = pack2(b0.z, b0.w);
            bp[2] = pack2(b1.x, b1.y); bp[3] = pack2(b1.z, b1.w);
            #pragma unroll
            for (int i = 0; i < 8; i++) {
                uint64_t ad = pack2(av[i], av[i]);
                #pragma unroll
                for (int j = 0; j < 4; j++)
                    acc[i][j] = fma2(ad, bp[j], acc[i][j]);
            }
        }
        __syncthreads();
    }

    // Write back
    #pragma unroll
    for (int i = 0; i < 8; i++) {
        int row = m0 + ty * 8 + i;
        float f0, f1, f2, f3, f4, f5, f6, f7;
        unpack2(acc[i][0], f0, f1); unpack2(acc[i][1], f2, f3);
        unpack2(acc[i][2], f4, f5); unpack2(acc[i][3], f6, f7);
        *(float4*)&OUT[(size_t)row * 512 + n0 + tx * 8]     = make_float4(f0, f1, f2, f3);
        *(float4*)&OUT[(size_t)row * 512 + n0 + tx * 8 + 4] = make_float4(f4, f5, f6, f7);
    }
}

// ============================================================
// Recurrent kernel: 16 clusters x 8 CTAs, 512 thr/CTA.
// Each CTA: 2 batches, 64 W3-columns register-resident.
// Per step: P1 logits partials -> csync -> P2 softmax+htilde -> csync
//           -> P3 gather htilde + GEMM g = htilde @ W3.
// ============================================================
__global__ __launch_bounds__(RTHREADS, 1) __cluster_dims__(RANKS, 1, 1)
void recurrent_kernel(const float* __restrict__ Hm,
                      const float* __restrict__ v,
                      const float* __restrict__ W3,
                      float* __restrict__ out)
{
    __shared__ float hts[BPC][D];                 // full htilde vectors (gathered)
    __shared__ float ghist[NS][BPC][COLS];        // ring: g_j = htilde_j @ W3 (our cols)
    __shared__ float thist[NS][BPC][COLS];        // ring: htilde_j (our cols)
    __shared__ float red[32][BPC * COLS];         // GEMM k-partition reduction
    __shared__ float vsm[COLS];
    __shared__ float ssm[BPC * NS];
    __shared__ float wsm[BPC][NS];

    const int tid  = threadIdx.x;
    const int rank = blockIdx.x & (RANKS - 1);
    const int cl   = blockIdx.x / RANKS;
    const int col0 = rank * COLS;
    const int b0   = cl * BPC;

    const int jg = tid & 15;    // 16 groups of 4 cols
    const int kp = tid >> 4;    // 32 k-partitions of 16

    // W3 slice -> registers, packed in f32x2 pairs
    uint64_t w3p[16][2];
    #pragma unroll
    for (int kk = 0; kk < 16; kk++) {
        float4 w = *(const float4*)&W3[(size_t)(kp * 16 + kk) * D + col0 + jg * 4];
        w3p[kk][0] = pack2(w.x, w.y);
        w3p[kk][1] = pack2(w.z, w.w);
    }
    if (tid < COLS) vsm[tid] = v[col0 + tid];
    for (int i = tid; i < NS * BPC * COLS; i += RTHREADS) {
        ((float*)ghist)[i] = 0.f;
        ((float*)thist)[i] = 0.f;
    }
    __syncthreads();

    const int warp = tid >> 5, lane = tid & 31;

    for (int t = 0; t < S; t++) {
        // ---------- Phase 1: logit partials  s[b][i] over our 64 cols ----------
        if (warp < BPC * NS) {
            const int bl = warp / NS, i = warp % NS;
            const int b = b0 + bl;
            const int j = t - NS + i;
            const int d0 = lane * 2;
            float2 c2 = *(const float2*)&g_C[((size_t)b * S + t) * D + col0 + d0];
            float x0 = c2.x, x1 = c2.y;
            if (j >= 0) {
                float2 a2 = *(const float2*)&g_A[((size_t)b * S + j) * D + col0 + d0];
                const int sl = j % NS;
                x0 += a2.x + ghist[sl][bl][d0];
                x1 += a2.y + ghist[sl][bl][d0 + 1];
            }
            float val = tanhf(x0) * vsm[d0] + tanhf(x1) * vsm[d0 + 1];
            #pragma unroll
            for (int o = 16; o > 0; o >>= 1)
                val += __shfl_down_sync(0xffffffffu, val, o);
            if (lane == 0)
                __stcg(&g_Spart[(b * NS + i) * RANKS + rank], val);
        }
        __threadfence();
        asm volatile("barrier.cluster.arrive.aligned;" ::: "memory");
        asm volatile("barrier.cluster.wait.aligned;" ::: "memory");

        // ---------- Phase 2: softmax + htilde ----------
        if (tid < BPC * NS) {
            const int bl = tid / NS, i = tid % NS;
            const int b = b0 + bl;
            float s = 0.f;
            #pragma unroll
            for (int r = 0; r < RANKS; r++)
                s += __ldcg(&g_Spart[(b * NS + i) * RANKS + r]);
            ssm[tid] = s;
        }
        __syncthreads();
        if (tid < BPC) {
            float mx = -1e30f;
            #pragma unroll
            for (int i = 0; i < NS; i++) mx = fmaxf(mx, ssm[tid * NS + i]);
            float e[NS], sum = 0.f;
            #pragma unroll
            for (int i = 0; i < NS; i++) { e[i] = expf(ssm[tid * NS + i] - mx); sum += e[i]; }
            float inv = 1.f / sum;
            #pragma unroll
            for (int i = 0; i < NS; i++) wsm[tid][i] = e[i] * inv;
        }
        __syncthreads();
        if (tid < BPC * COLS) {
            const int bl = tid / COLS, dd = tid % COLS;
            const int b = b0 + bl;
            float hh = 0.f;
            #pragma unroll
            for (int i = 0; i < NS; i++) {
                int j = t - NS + i;
                if (j >= 0) hh += wsm[bl][i] * thist[j % NS][bl][dd];
            }
            float hv = Hm[((size_t)b * S + t) * D + col0 + dd] + fmaxf(hh, 0.f);
            thist[t % NS][bl][dd] = hv;
            __stcg(&g_ht[b * D + col0 + dd], hv);
            out[((size_t)b * S + t) * D + col0 + dd] = hv;
        }
        __threadfence();
        asm volatile("barrier.cluster.arrive.aligned;" ::: "memory");
        asm volatile("barrier.cluster.wait.aligned;" ::: "memory");

        // ---------- Phase 3: gather htilde, GEMM g = htilde @ W3slice ----------
        #pragma unroll
        for (int i = 0; i < (BPC * D) / RTHREADS; i++) {   // 2 iters
            int idx = i * RTHREADS + tid;
            int bl = idx / D, k = idx % D;
            hts[bl][k] = __ldcg(&g_ht[(b0 + bl) * D + k]);
        }
        __syncthreads();

        uint64_t acc00 = 0ull, acc01 = 0ull, acc10 = 0ull, acc11 = 0ull;
        #pragma unroll
        for (int kk = 0; kk < 16; kk++) {
            const int k = kp * 16 + kk;
            const float h0 = hts[0][k];
            const float h1 = hts[1][k];
            uint64_t a0 = pack2(h0, h0);
            uint64_t a1 = pack2(h1, h1);
            acc00 = fma2(a0, w3p[kk][0], acc00);
            acc01 = fma2(a0, w3p[kk][1], acc01);
            acc10 = fma2(a1, w3p[kk][0], acc10);
            acc11 = fma2(a1, w3p[kk][1], acc11);
        }
        {
            float f0, f1, f2, f3;
            unpack2(acc00, f0, f1); unpack2(acc01, f2, f3);
            *(float4*)&red[kp][0 * COLS + jg * 4] = make_float4(f0, f1, f2, f3);
            unpack2(acc10, f0, f1); unpack2(acc11, f2, f3);
            *(float4*)&red[kp][1 * COLS + jg * 4] = make_float4(f0, f1, f2, f3);
        }
        __syncthreads();
        if (tid < BPC * COLS) {
            const int bl = tid / COLS, dd = tid % COLS;
            float s = 0.f;
            #pragma unroll
            for (int r = 0; r < 32; r++) s += red[r][bl * COLS + dd];
            ghist[t % NS][bl][dd] = s;
        }
        __syncthreads();
    }
}

// ============================================================
// Launch
// ============================================================
extern "C" void kernel_launch(void* const* d_in, const int* in_sizes, int n_in,
                              void* d_out, int out_size)
{
    (void)in_sizes; (void)n_in; (void)out_size;
    const float* H  = (const float*)d_in[0];
    const float* v  = (const float*)d_in[1];
    const float* W1 = (const float*)d_in[2];
    const float* W2 = (const float*)d_in[3];
    const float* W3 = (const float*)d_in[4];
    float* out = (float*)d_out;

    // A = H@W1, C = H@W2
    precompute_kernel<<<dim3((B * S) / PM, 8), 256>>>(H, W1, W2);
    // Sequential recurrence (16 clusters x 8 CTAs)
    recurrent_kernel<<<NCLUSTERS * RANKS, RTHREADS>>>(H, v, W3, out);
}

// round 2
// speedup vs baseline: 1.5459x; 1.5459x over previous
#include <cuda_runtime.h>
#include <cstdint>

#define DEV_INLINE __device__ __forceinline__

// Problem constants
constexpr int B  = 32;
constexpr int S  = 512;
constexpr int D  = 512;
constexpr int NS = 5;

// Recurrent kernel tiling
constexpr int RANKS     = 8;            // CTAs per cluster
constexpr int BPC       = 2;            // batches per cluster
constexpr int NCLUSTERS = B / BPC;      // 16
constexpr int COLS      = D / RANKS;    // 64 columns per CTA
constexpr int RTHREADS  = 512;

// Scratch (static device arrays; no allocations allowed)
__device__ float g_A[(size_t)B * S * D];       // H @ W1
__device__ float g_C[(size_t)B * S * D];       // H @ W2

// ---------- helpers ----------
DEV_INLINE uint64_t pack2(float lo, float hi) {
    uint64_t r; asm("mov.b64 %0, {%1, %2};" : "=l"(r) : "f"(lo), "f"(hi)); return r;
}
DEV_INLINE void unpack2(uint64_t v, float& lo, float& hi) {
    asm("mov.b64 {%0, %1}, %2;" : "=f"(lo), "=f"(hi) : "l"(v));
}
DEV_INLINE uint64_t fma2(uint64_t a, uint64_t b, uint64_t c) {
    uint64_t d; asm("fma.rn.f32x2 %0, %1, %2, %3;" : "=l"(d) : "l"(a), "l"(b), "l"(c));
    return d;
}
DEV_INLINE uint32_t su32(const void* p) {
    uint32_t a;
    asm("{ .reg .u64 t; cvta.to.shared.u64 t, %1; cvt.u32.u64 %0, t; }" : "=r"(a) : "l"(p));
    return a;
}
DEV_INLINE void stc_f32(uint32_t saddr, int rank, float v) {
    asm volatile("{ .reg .b32 r; mapa.shared::cluster.u32 r, %0, %1; st.shared::cluster.f32 [r], %2; }"
                 :: "r"(saddr), "r"(rank), "f"(v) : "memory");
}
DEV_INLINE void stc_b64(uint32_t saddr, int rank, uint64_t v) {
    asm volatile("{ .reg .b32 r; mapa.shared::cluster.u32 r, %0, %1; st.shared::cluster.b64 [r], %2; }"
                 :: "r"(saddr), "r"(rank), "l"(v) : "memory");
}
DEV_INLINE void cluster_bar() {
    asm volatile("barrier.cluster.arrive.aligned;" ::: "memory");
    asm volatile("barrier.cluster.wait.aligned;"   ::: "memory");
}
// fast tanh via __expf, clamped so exp never overflows (tanh(15) == 1 to fp32)
DEV_INLINE float ftanh(float x) {
    x = fminf(15.f, fmaxf(-15.f, x));
    float e = __expf(x + x);
    return __fdividef(e - 1.f, e + 1.f);
}

// ============================================================
// Precompute: A = H @ W1, C = H @ W2   (fp32, f32x2 FMAs)
// ============================================================
constexpr int PM = 128, PN = 128, PK = 16;

__global__ __launch_bounds__(256) void precompute_kernel(
    const float* __restrict__ Hm,
    const float* __restrict__ W1,
    const float* __restrict__ W2)
{
    __shared__ float As[PK][PM];
    __shared__ float Bs[PK][PN];

    const int tid   = threadIdx.x;
    const int which = blockIdx.y >> 2;          // 0 -> W1/A, 1 -> W2/C
    const int n0    = (blockIdx.y & 3) * PN;
    const int m0    = blockIdx.x * PM;
    const float* W  = which ? W2 : W1;
    float* OUT      = which ? g_C : g_A;

    const int tx = tid & 15;
    const int ty = tid >> 4;

    uint64_t acc[8][4];
    #pragma unroll
    for (int i = 0; i < 8; i++)
        #pragma unroll
        for (int j = 0; j < 4; j++) acc[i][j] = 0ull;

    for (int kt = 0; kt < 512; kt += PK) {
        #pragma unroll
        for (int i = 0; i < 2; i++) {
            int idx4 = i * 256 + tid;
            int m  = idx4 >> 2;
            int kq = (idx4 & 3) * 4;
            float4 vv = *(const float4*)&Hm[(size_t)(m0 + m) * 512 + kt + kq];
            As[kq + 0][m] = vv.x; As[kq + 1][m] = vv.y;
            As[kq + 2][m] = vv.z; As[kq + 3][m] = vv.w;
        }
        #pragma unroll
        for (int i = 0; i < 2; i++) {
            int idx4 = i * 256 + tid;
            int n4 = (idx4 & 31) * 4;
            int k  = idx4 >> 5;
            *(float4*)&Bs[k][n4] = *(const float4*)&W[(size_t)(kt + k) * 512 + n0 + n4];
        }
        __syncthreads();

        #pragma unroll
        for (int k = 0; k < PK; k++) {
            float4 a0 = *(const float4*)&As[k][ty * 8];
            float4 a1 = *(const float4*)&As[k][ty * 8 + 4];
            float4 b0 = *(const float4*)&Bs[k][tx * 8];
            float4 b1 = *(const float4*)&Bs[k][tx * 8 + 4];
            float av[8] = {a0.x, a0.y, a0.z, a0.w, a1.x, a1.y, a1.z, a1.w};
            uint64_t bp[4];
            bp[0] = pack2(b0.x, b0.y); bp[1] = pack2(b0.z, b0.w);
            bp[2] = pack2(b1.x, b1.y); bp[3] = pack2(b1.z, b1.w);
            #pragma unroll
            for (int i = 0; i < 8; i++) {
                uint64_t ad = pack2(av[i], av[i]);
                #pragma unroll
                for (int j = 0; j < 4; j++)
                    acc[i][j] = fma2(ad, bp[j], acc[i][j]);
            }
        }
        __syncthreads();
    }

    #pragma unroll
    for (int i = 0; i < 8; i++) {
        int row = m0 + ty * 8 + i;
        float f0, f1, f2, f3, f4, f5, f6, f7;
        unpack2(acc[i][0], f0, f1); unpack2(acc[i][1], f2, f3);
        unpack2(acc[i][2], f4, f5); unpack2(acc[i][3], f6, f7);
        *(float4*)&OUT[(size_t)row * 512 + n0 + tx * 8]     = make_float4(f0, f1, f2, f3);
        *(float4*)&OUT[(size_t)row * 512 + n0 + tx * 8 + 4] = make_float4(f4, f5, f6, f7);
    }
}

// ============================================================
// Recurrent kernel: 16 clusters x 8 CTAs, 512 thr/CTA.
// K-partitioned W3: CTA rank r holds W3 rows [r*64, r*64+64) for ALL
// 512 output columns (thread t owns column t). htilde is never
// exchanged; only 10 logit partials and a 128-float partial-g slice
// cross CTAs per step, via DSMEM + cluster barriers.
// ============================================================
__global__ __launch_bounds__(RTHREADS, 1) __cluster_dims__(RANKS, 1, 1)
void recurrent_kernel(const float* __restrict__ Hm,
                      const float* __restrict__ v,
                      const float* __restrict__ W3,
                      float* __restrict__ out)
{
    __shared__ float2 hts2[COLS];                 // htilde own cols, (b0,b1) packed
    __shared__ float  thist[NS][BPC][COLS];       // htilde history (own cols)
    __shared__ float  ghist[NS][BPC][COLS];       // summed g history (own cols)
    __shared__ float2 gpart2[RANKS][COLS];        // partial-g receive buffer
    __shared__ float  spart[BPC][NS][RANKS];      // partial-logit receive buffer
    __shared__ float  pbufA[2][BPC * NS][COLS];   // prefetched g_A rows
    __shared__ float  pbufC[2][BPC][COLS];        // prefetched g_C rows
    __shared__ float  hbuf[2][BPC][COLS];         // prefetched H rows
    __shared__ float  vsm[COLS];
    __shared__ float  ssm[BPC * NS];
    __shared__ float  wsm[BPC][NS];

    const int tid  = threadIdx.x;
    const int warp = tid >> 5, lane = tid & 31;
    const int rank = blockIdx.x & (RANKS - 1);
    const int cl   = blockIdx.x >> 3;
    const int col0 = rank * COLS;
    const int b0   = cl * BPC;

    // W3 slice: thread owns output column n = tid, k-rows col0..col0+63
    float w3c[COLS];
    #pragma unroll
    for (int kk = 0; kk < COLS; kk++)
        w3c[kk] = W3[(size_t)(col0 + kk) * D + tid];

    if (tid < COLS) vsm[tid] = v[col0 + tid];

    // Prologue prefetch for t = 0 (only C and H rows matter; A rows have j<0)
    if (warp >= 10) {
        int idx = tid - 320, row = idx >> 4, q = (idx & 15) * 4;
        if (row >= 10) {
            int bl = row - 10;
            *(float4*)&pbufC[0][bl][q] =
                *(const float4*)&g_C[((size_t)(b0 + bl) * S + 0) * D + col0 + q];
        }
        if (idx < 32) {
            int bl = idx >> 4, q2 = (idx & 15) * 4;
            *(float4*)&hbuf[0][bl][q2] =
                *(const float4*)&Hm[((size_t)(b0 + bl) * S + 0) * D + col0 + q2];
        }
    }
    __syncthreads();

    const uint32_t gpush_addr = su32(&gpart2[rank][tid & 63]);
    const int      gpush_rank = tid >> 6;

    for (int t = 0; t < S; t++) {
        const int par = t & 1;
        const int tp  = t + 1;

        // ================= R1 =================
        // Loader warps (10-15): issue LDGs for step t+1 (held in regs)
        float4 pvA = make_float4(0.f, 0.f, 0.f, 0.f);
        float4 pvH = make_float4(0.f, 0.f, 0.f, 0.f);
        int pfrow = -1; bool pfH = false;
        if (warp >= 10 && tp < S) {
            int idx = tid - 320, row = idx >> 4, q = (idx & 15) * 4;
            if (row < 10) {
                int bl = row / NS, i = row - bl * NS, j = tp - NS + i;
                if (j >= 0) {
                    pvA = *(const float4*)&g_A[((size_t)(b0 + bl) * S + j) * D + col0 + q];
                    pfrow = row;
                }
            } else {
                int bl = row - 10;
                pvA = *(const float4*)&g_C[((size_t)(b0 + bl) * S + tp) * D + col0 + q];
                pfrow = row;
            }
            if (idx < 32) {
                int bl = idx >> 4, q2 = (idx & 15) * 4;
                pvH = *(const float4*)&Hm[((size_t)(b0 + bl) * S + tp) * D + col0 + q2];
                pfH = true;
            }
        }

        // P1: logit partials over our 64 cols; warp i==NS-1 folds in the
        // 8-way sum of last step's partial-g pushes (and records ghist).
        if (warp < BPC * NS) {
            const int bl = warp / NS, i = warp - bl * NS;
            const int j  = t - NS + i;
            const int d0 = lane * 2;
            float2 c2 = *(float2*)&pbufC[par][bl][d0];
            float x0 = c2.x, x1 = c2.y;
            if (j >= 0) {
                float2 a2 = *(float2*)&pbufA[par][warp][d0];
                float g0, g1;
                const int sl = j % NS;
                if (i == NS - 1) {
                    g0 = 0.f; g1 = 0.f;
                    #pragma unroll
                    for (int r = 0; r < RANKS; r++) {
                        float4 qv = *(float4*)&gpart2[r][d0];
                        if (bl == 0) { g0 += qv.x; g1 += qv.z; }
                        else         { g0 += qv.y; g1 += qv.w; }
                    }
                    ghist[sl][bl][d0]     = g0;
                    ghist[sl][bl][d0 + 1] = g1;
                } else {
                    g0 = ghist[sl][bl][d0];
                    g1 = ghist[sl][bl][d0 + 1];
                }
                x0 += a2.x + g0;
                x1 += a2.y + g1;
            }
            float val = ftanh(x0) * vsm[d0] + ftanh(x1) * vsm[d0 + 1];
            #pragma unroll
            for (int o = 16; o > 0; o >>= 1)
                val += __shfl_down_sync(0xffffffffu, val, o);
            if (lane == 0) {
                uint32_t a = su32(&spart[bl][i][rank]);
                #pragma unroll
                for (int r = 0; r < RANKS; r++) stc_f32(a, r, val);
            }
        }
        cluster_bar();   // A: s-partials visible everywhere

        // ================= R2 =================
        // warp 0: sum partials + softmax
        if (warp == 0) {
            if (lane < BPC * NS) {
                const int bl = lane / NS, i = lane - bl * NS;
                float4 u0 = *(float4*)&spart[bl][i][0];
                float4 u1 = *(float4*)&spart[bl][i][4];
                ssm[lane] = (u0.x + u0.y + u0.z + u0.w) + (u1.x + u1.y + u1.z + u1.w);
            }
            __syncwarp();
            if (lane < BPC) {
                float s[NS];
                #pragma unroll
                for (int i = 0; i < NS; i++) s[i] = ssm[lane * NS + i];
                float m = s[0];
                #pragma unroll
                for (int i = 1; i < NS; i++) m = fmaxf(m, s[i]);
                float e[NS], sum = 0.f;
                #pragma unroll
                for (int i = 0; i < NS; i++) { e[i] = __expf(s[i] - m); sum += e[i]; }
                float inv = __fdividef(1.f, sum);
                #pragma unroll
                for (int i = 0; i < NS; i++) wsm[lane][i] = e[i] * inv;
            }
        }
        // loader warps: deposit prefetched rows for t+1
        if (warp >= 10 && tp < S) {
            int idx = tid - 320, q = (idx & 15) * 4;
            if (pfrow >= 0) {
                if (pfrow < 10) *(float4*)&pbufA[par ^ 1][pfrow][q]      = pvA;
                else            *(float4*)&pbufC[par ^ 1][pfrow - 10][q] = pvA;
            }
            if (pfH) {
                int bl = idx >> 4, q2 = (idx & 15) * 4;
                *(float4*)&hbuf[par ^ 1][bl][q2] = pvH;
            }
        }
        __syncthreads();

        // P2: htilde (own cols only — never leaves the CTA)
        if (tid < BPC * COLS) {
            const int bl = tid >> 6, dd = tid & 63;
            float hh = 0.f;
            #pragma unroll
            for (int i = 0; i < NS; i++) {
                int j = t - NS + i;
                if (j >= 0) hh += wsm[bl][i] * thist[j % NS][bl][dd];
            }
            float hv = hbuf[par][bl][dd] + fmaxf(hh, 0.f);
            thist[t % NS][bl][dd] = hv;
            ((float*)&hts2[dd])[bl] = hv;
            out[((size_t)(b0 + bl) * S + t) * D + col0 + dd] = hv;
        }
        __syncthreads();

        // P3: partial g = htilde(own 64 k) @ W3(own rows), full 512 cols;
        // thread owns column n = tid, batches packed in (acc0, acc1).
        float acc0 = 0.f, acc1 = 0.f;
        #pragma unroll
        for (int kk = 0; kk < COLS; kk++) {
            float2 h = hts2[kk];
            acc0 = fmaf(h.x, w3c[kk], acc0);
            acc1 = fmaf(h.y, w3c[kk], acc1);
        }
        stc_b64(gpush_addr, gpush_rank, pack2(acc0, acc1));
        cluster_bar();   // B: g-partials visible everywhere
    }
}

// ============================================================
// Launch
// ============================================================
extern "C" void kernel_launch(void* const* d_in, const int* in_sizes, int n_in,
                              void* d_out, int out_size)
{
    (void)in_sizes; (void)n_in; (void)out_size;
    const float* H  = (const float*)d_in[0];
    const float* v  = (const float*)d_in[1];
    const float* W1 = (const float*)d_in[2];
    const float* W2 = (const float*)d_in[3];
    const float* W3 = (const float*)d_in[4];
    float* out = (float*)d_out;

    precompute_kernel<<<dim3((B * S) / PM, 8), 256>>>(H, W1, W2);
    recurrent_kernel<<<NCLUSTERS * RANKS, RTHREADS>>>(H, v, W3, out);
}